// round 1
// baseline (speedup 1.0000x reference)
#include <cuda_runtime.h>
#include <math_constants.h>

#define B_  4
#define S_  4096
#define D_  256
#define H_  4
#define DH_ 64
#define MT_ (B_ * S_)   // 16384 rows

// ---------------------------------------------------------------------------
// Scratch (static device globals; no runtime allocation allowed)
// ---------------------------------------------------------------------------
__device__ float g_Q[(size_t)B_ * H_ * S_ * DH_];   // [b][h][s][dh], pre-scaled by 1/8
__device__ float g_K[(size_t)B_ * H_ * S_ * DH_];   // [b][h][s][dh]
__device__ float g_V[(size_t)B_ * H_ * S_ * DH_];   // [b][h][s][dh]
__device__ float g_attn[(size_t)B_ * S_ * D_];      // [b][s][h*DH+dh]

// ---------------------------------------------------------------------------
// Kernel 1: fused QKV projection.  C[16384,256] = X @ W + b, written head-split.
// grid (MT/64, H, 3), block 256. 64x64 CTA tile, 4x4 per-thread micro-tile.
// ---------------------------------------------------------------------------
__global__ void __launch_bounds__(256) qkv_gemm(
    const float* __restrict__ X,
    const float* __restrict__ Wq, const float* __restrict__ bq,
    const float* __restrict__ Wk, const float* __restrict__ bk,
    const float* __restrict__ Wv, const float* __restrict__ bv)
{
    __shared__ float Xt[32][68];   // k-major: Xt[k][m]  (pad 68 -> 16B-aligned rows)
    __shared__ float Ws[32][68];   // natural: Ws[k][n]

    const float* W; const float* bias; float* out; float qscale;
    if (blockIdx.z == 0)      { W = Wq; bias = bq; out = g_Q; qscale = 0.125f; }
    else if (blockIdx.z == 1) { W = Wk; bias = bk; out = g_K; qscale = 1.0f;   }
    else                      { W = Wv; bias = bv; out = g_V; qscale = 1.0f;   }

    const int m0 = blockIdx.x * 64;
    const int h  = blockIdx.y;          // 64-wide col tile == one head
    const int n0 = h * 64;
    const int tid = threadIdx.x;
    const int tx = tid & 15, ty = tid >> 4;

    float acc[4][4] = {};

    for (int kk = 0; kk < D_; kk += 32) {
        #pragma unroll
        for (int it = 0; it < 8; it++) {
            int idx = tid + it * 256;
            {   // X tile: coalesced along k, transposed into smem
                int r = idx >> 5, k = idx & 31;
                Xt[k][r] = X[(size_t)(m0 + r) * D_ + kk + k];
            }
            {   // W tile: coalesced along n
                int k = idx >> 6, n = idx & 63;
                Ws[k][n] = W[(size_t)(kk + k) * D_ + n0 + n];
            }
        }
        __syncthreads();
        #pragma unroll
        for (int k = 0; k < 32; k++) {
            float4 a4 = *(const float4*)&Xt[k][ty * 4];
            float4 b4 = *(const float4*)&Ws[k][tx * 4];
            float av[4] = {a4.x, a4.y, a4.z, a4.w};
            float bw[4] = {b4.x, b4.y, b4.z, b4.w};
            #pragma unroll
            for (int i = 0; i < 4; i++)
                #pragma unroll
                for (int j = 0; j < 4; j++)
                    acc[i][j] = fmaf(av[i], bw[j], acc[i][j]);
        }
        __syncthreads();
    }

    // epilogue: head-split layout [b][h][s][dh], Q pre-scaled by 1/sqrt(Dh)
    const int bb = m0 >> 12;           // m = b*S + s, S = 4096
    const int sbase = m0 & (S_ - 1);
    #pragma unroll
    for (int i = 0; i < 4; i++) {
        const int s = sbase + ty * 4 + i;
        #pragma unroll
        for (int j = 0; j < 4; j++) {
            const int dh = tx * 4 + j;
            out[((size_t)(bb * H_ + h) * S_ + s) * DH_ + dh] =
                (acc[i][j] + bias[n0 + dh]) * qscale;
        }
    }
}

// ---------------------------------------------------------------------------
// Kernel 2: flash attention, fp32, online softmax.
// grid (S/64, B*H), block 256.  Bq = Bk = 64, Dh = 64.
// Dynamic smem: Qt/Kt (d-major), Vs (k-major), Ps (scores), row stats.
// ---------------------------------------------------------------------------
#define ATTN_SMEM_FLOATS (4 * 64 * 68 + 3 * 64 + 256)
#define ATTN_SMEM_BYTES  (ATTN_SMEM_FLOATS * 4)

__global__ void __launch_bounds__(256) attn_kernel()
{
    extern __shared__ float sm[];
    float (*Qt)[68] = (float(*)[68])(sm);                // Qt[d][r]
    float (*Kt)[68] = (float(*)[68])(sm + 1 * 64 * 68);  // Kt[d][c]
    float (*Vs)[68] = (float(*)[68])(sm + 2 * 64 * 68);  // Vs[k][c]
    float (*Ps)[68] = (float(*)[68])(sm + 3 * 64 * 68);  // Ps[r][k]
    float* m_s  = sm + 4 * 64 * 68;   // 64  running row max
    float* l_s  = m_s + 64;           // 64  running row sum
    float* c_s  = l_s + 64;           // 64  correction factor
    float* red4 = c_s + 64;           // 256 partial reductions

    const int tid = threadIdx.x;
    const int tx = tid & 15, ty = tid >> 4;
    const int rr = tid >> 2, qq = tid & 3;   // softmax: 4 threads per row
    const int bh = blockIdx.y;
    const int q0 = blockIdx.x * 64;

    const float* Qg = g_Q + (size_t)bh * S_ * DH_;
    const float* Kg = g_K + (size_t)bh * S_ * DH_;
    const float* Vg = g_V + (size_t)bh * S_ * DH_;

    // load Q tile transposed (already pre-scaled by 1/8 in qkv_gemm)
    #pragma unroll
    for (int it = 0; it < 16; it++) {
        int idx = tid + it * 256;
        int r = idx >> 6, d = idx & 63;
        Qt[d][r] = Qg[(size_t)(q0 + r) * DH_ + d];
    }
    if (tid < 64) { m_s[tid] = -CUDART_INF_F; l_s[tid] = 0.0f; }

    float acc[4][4] = {};

    for (int j0 = 0; j0 < S_; j0 += 64) {
        __syncthreads();   // Qt/stats ready (iter 0); previous tile fully consumed
        #pragma unroll
        for (int it = 0; it < 16; it++) {
            int idx = tid + it * 256;
            int r = idx >> 6, d = idx & 63;
            Kt[d][r] = Kg[(size_t)(j0 + r) * DH_ + d];
            Vs[r][d] = Vg[(size_t)(j0 + r) * DH_ + d];
        }
        __syncthreads();

        // ---- S = Q K^T (pre-scaled) ----
        float s[4][4] = {};
        #pragma unroll 8
        for (int d = 0; d < 64; d++) {
            float4 a4 = *(const float4*)&Qt[d][ty * 4];
            float4 b4 = *(const float4*)&Kt[d][tx * 4];
            float av[4] = {a4.x, a4.y, a4.z, a4.w};
            float bw[4] = {b4.x, b4.y, b4.z, b4.w};
            #pragma unroll
            for (int i = 0; i < 4; i++)
                #pragma unroll
                for (int j = 0; j < 4; j++)
                    s[i][j] = fmaf(av[i], bw[j], s[i][j]);
        }
        #pragma unroll
        for (int i = 0; i < 4; i++)
            #pragma unroll
            for (int j = 0; j < 4; j++)
                Ps[ty * 4 + i][tx * 4 + j] = s[i][j];
        __syncthreads();

        // ---- online softmax ----
        // A: partial row max (4 threads / row, 16 cols each)
        {
            float mx = -CUDART_INF_F;
            #pragma unroll
            for (int c = 0; c < 16; c++)
                mx = fmaxf(mx, Ps[rr][qq * 16 + c]);
            red4[rr * 4 + qq] = mx;
        }
        __syncthreads();
        // B: finalize row max + correction
        if (tid < 64) {
            float m_old = m_s[tid];
            float mnew = fmaxf(fmaxf(red4[tid * 4 + 0], red4[tid * 4 + 1]),
                               fmaxf(red4[tid * 4 + 2], red4[tid * 4 + 3]));
            mnew = fmaxf(mnew, m_old);
            m_s[tid] = mnew;
            c_s[tid] = __expf(m_old - mnew);
        }
        __syncthreads();
        // C: exponentiate in place + partial row sum
        {
            float mrow = m_s[rr];
            float sum = 0.0f;
            #pragma unroll
            for (int c = 0; c < 16; c++) {
                float p = __expf(Ps[rr][qq * 16 + c] - mrow);
                Ps[rr][qq * 16 + c] = p;
                sum += p;
            }
            red4[rr * 4 + qq] = sum;
        }
        __syncthreads();
        // D: update running denominator
        if (tid < 64) {
            l_s[tid] = l_s[tid] * c_s[tid]
                     + red4[tid * 4 + 0] + red4[tid * 4 + 1]
                     + red4[tid * 4 + 2] + red4[tid * 4 + 3];
        }

        // ---- rescale accumulator, O += P V ----
        float cr[4];
        #pragma unroll
        for (int i = 0; i < 4; i++) cr[i] = c_s[ty * 4 + i];
        #pragma unroll
        for (int i = 0; i < 4; i++)
            #pragma unroll
            for (int j = 0; j < 4; j++)
                acc[i][j] *= cr[i];

        #pragma unroll 4
        for (int k = 0; k < 64; k++) {
            float4 b4 = *(const float4*)&Vs[k][tx * 4];
            float bw[4] = {b4.x, b4.y, b4.z, b4.w};
            float av[4];
            #pragma unroll
            for (int i = 0; i < 4; i++) av[i] = Ps[ty * 4 + i][k];
            #pragma unroll
            for (int i = 0; i < 4; i++)
                #pragma unroll
                for (int j = 0; j < 4; j++)
                    acc[i][j] = fmaf(av[i], bw[j], acc[i][j]);
        }
    }
    __syncthreads();   // l_s final

    float invl[4];
    #pragma unroll
    for (int i = 0; i < 4; i++) invl[i] = 1.0f / l_s[ty * 4 + i];

    const int bb = bh >> 2, h = bh & 3;
    float* outp = g_attn + ((size_t)bb * S_ + q0) * D_ + h * DH_;
    #pragma unroll
    for (int i = 0; i < 4; i++)
        #pragma unroll
        for (int j = 0; j < 4; j++)
            outp[(size_t)(ty * 4 + i) * D_ + tx * 4 + j] = acc[i][j] * invl[i];
}

// ---------------------------------------------------------------------------
// Kernel 3: output projection.  out[16384,256] = g_attn @ Wo + bo
// ---------------------------------------------------------------------------
__global__ void __launch_bounds__(256) out_gemm(
    const float* __restrict__ Wo, const float* __restrict__ bo,
    float* __restrict__ out)
{
    __shared__ float Xt[32][68];
    __shared__ float Ws[32][68];

    const int m0 = blockIdx.x * 64;
    const int n0 = blockIdx.y * 64;
    const int tid = threadIdx.x;
    const int tx = tid & 15, ty = tid >> 4;

    float acc[4][4] = {};

    for (int kk = 0; kk < D_; kk += 32) {
        #pragma unroll
        for (int it = 0; it < 8; it++) {
            int idx = tid + it * 256;
            {
                int r = idx >> 5, k = idx & 31;
                Xt[k][r] = g_attn[(size_t)(m0 + r) * D_ + kk + k];
            }
            {
                int k = idx >> 6, n = idx & 63;
                Ws[k][n] = Wo[(size_t)(kk + k) * D_ + n0 + n];
            }
        }
        __syncthreads();
        #pragma unroll
        for (int k = 0; k < 32; k++) {
            float4 a4 = *(const float4*)&Xt[k][ty * 4];
            float4 b4 = *(const float4*)&Ws[k][tx * 4];
            float av[4] = {a4.x, a4.y, a4.z, a4.w};
            float bw[4] = {b4.x, b4.y, b4.z, b4.w};
            #pragma unroll
            for (int i = 0; i < 4; i++)
                #pragma unroll
                for (int j = 0; j < 4; j++)
                    acc[i][j] = fmaf(av[i], bw[j], acc[i][j]);
        }
        __syncthreads();
    }

    #pragma unroll
    for (int i = 0; i < 4; i++)
        #pragma unroll
        for (int j = 0; j < 4; j++)
            out[(size_t)(m0 + ty * 4 + i) * D_ + n0 + tx * 4 + j] =
                acc[i][j] + bo[n0 + tx * 4 + j];
}

// ---------------------------------------------------------------------------
// Launch
// ---------------------------------------------------------------------------
extern "C" void kernel_launch(void* const* d_in, const int* in_sizes, int n_in,
                              void* d_out, int out_size)
{
    const float* X  = (const float*)d_in[0];
    const float* Wq = (const float*)d_in[1];
    const float* bq = (const float*)d_in[2];
    const float* Wk = (const float*)d_in[3];
    const float* bk = (const float*)d_in[4];
    const float* Wv = (const float*)d_in[5];
    const float* bv = (const float*)d_in[6];
    const float* Wo = (const float*)d_in[7];
    const float* bo = (const float*)d_in[8];
    float* out = (float*)d_out;

    cudaFuncSetAttribute(attn_kernel,
                         cudaFuncAttributeMaxDynamicSharedMemorySize,
                         ATTN_SMEM_BYTES);

    qkv_gemm<<<dim3(MT_ / 64, H_, 3), 256>>>(X, Wq, bq, Wk, bk, Wv, bv);
    attn_kernel<<<dim3(S_ / 64, B_ * H_), 256, ATTN_SMEM_BYTES>>>();
    out_gemm<<<dim3(MT_ / 64, D_ / 64), 256>>>(Wo, bo, out);
}